// round 1
// baseline (speedup 1.0000x reference)
#include <cuda_runtime.h>
#include <math.h>

#define B_  4
#define M_  1024
#define R_  256
#define H_  16
#define DH_ 64
#define D_  1024   // H_*DH_

// Scratch for q/k/v in (b,h,m,dd) layout. Static device globals (no allocs allowed).
__device__ float g_q[B_ * H_ * M_ * DH_];
__device__ float g_k[B_ * H_ * M_ * DH_];
__device__ float g_v[B_ * H_ * M_ * DH_];

// ---------------------------------------------------------------------------
// Kernel 1: fused SVD projection + bias + RoPE.
//   C[(b,m),(h,dd)] = P[(b,m),r] @ V[r,(h,dd)] + bias[(h,dd)], then RoPE for q,k.
// Tile 64x64, K-step 32. 256 threads as 16x16; thread (ty,tx) owns rows
// ty*4+i and columns tx+16*j. Columns j and j+2 differ by 32 -> RoPE pair is
// thread-local. blockIdx.x == head (N-tile), blockIdx.y == (b,m) tile,
// blockIdx.z selects q/k/v.
// ---------------------------------------------------------------------------
__global__ __launch_bounds__(256) void svd_proj_kernel(
    const float* __restrict__ Pq, const float* __restrict__ Pk, const float* __restrict__ Pv,
    const float* __restrict__ Vq, const float* __restrict__ Vk, const float* __restrict__ Vv,
    const float* __restrict__ bq, const float* __restrict__ bk, const float* __restrict__ bv,
    const int* __restrict__ pos_ids)
{
    const int sel = blockIdx.z;
    const float* A    = (sel == 0) ? Pq : (sel == 1) ? Pk : Pv;
    const float* Bm   = (sel == 0) ? Vq : (sel == 1) ? Vk : Vv;
    const float* bias = (sel == 0) ? bq : (sel == 1) ? bk : bv;
    float* outg       = (sel == 0) ? g_q : (sel == 1) ? g_k : g_v;

    __shared__ float sA[64 * 32];   // [row][k] stride 32
    __shared__ float sB[32 * 64];   // [k][col] stride 64

    const int tid = threadIdx.x;
    const int ty  = tid >> 4;
    const int tx  = tid & 15;
    const int h   = blockIdx.x;       // 64-wide N tile == one head
    const int n0  = h * 64;
    const int bm0 = blockIdx.y * 64;  // combined (b*M + m) base
    const int b   = bm0 / M_;
    const int mbase = bm0 % M_;

    float acc[4][4];
#pragma unroll
    for (int i = 0; i < 4; i++)
#pragma unroll
        for (int j = 0; j < 4; j++) acc[i][j] = 0.0f;

    for (int k0 = 0; k0 < R_; k0 += 32) {
#pragma unroll
        for (int t = 0; t < 8; t++) {
            int idx = tid + t * 256;
            sA[idx] = A[(size_t)(bm0 + (idx >> 5)) * R_ + k0 + (idx & 31)];
        }
#pragma unroll
        for (int t = 0; t < 8; t++) {
            int idx = tid + t * 256;
            sB[idx] = Bm[(size_t)(k0 + (idx >> 6)) * D_ + n0 + (idx & 63)];
        }
        __syncthreads();
#pragma unroll
        for (int kk = 0; kk < 32; kk++) {
            float a0 = sA[(ty * 4 + 0) * 32 + kk];
            float a1 = sA[(ty * 4 + 1) * 32 + kk];
            float a2 = sA[(ty * 4 + 2) * 32 + kk];
            float a3 = sA[(ty * 4 + 3) * 32 + kk];
            float b0 = sB[kk * 64 + tx];
            float b1 = sB[kk * 64 + tx + 16];
            float b2 = sB[kk * 64 + tx + 32];
            float b3 = sB[kk * 64 + tx + 48];
            acc[0][0] += a0 * b0; acc[0][1] += a0 * b1; acc[0][2] += a0 * b2; acc[0][3] += a0 * b3;
            acc[1][0] += a1 * b0; acc[1][1] += a1 * b1; acc[1][2] += a1 * b2; acc[1][3] += a1 * b3;
            acc[2][0] += a2 * b0; acc[2][1] += a2 * b1; acc[2][2] += a2 * b2; acc[2][3] += a2 * b3;
            acc[3][0] += a3 * b0; acc[3][1] += a3 * b1; acc[3][2] += a3 * b2; acc[3][3] += a3 * b3;
        }
        __syncthreads();
    }

    // Epilogue: bias (+ RoPE for q,k). Write layout (b,h,m,dd).
    const bool doRope = (sel < 2);
    // log2(10000) for inv_freq = 10000^(-dd/32) = exp2(-dd/32 * log2(10000))
    const float L2T = 13.287712379549449f / 32.0f;

#pragma unroll
    for (int i = 0; i < 4; i++) {
        const int m = mbase + ty * 4 + i;
        const size_t base = ((size_t)(b * H_ + h) * M_ + m) * DH_;
        if (doRope) {
            const float pos = (float)pos_ids[b * M_ + m];
#pragma unroll
            for (int jp = 0; jp < 2; jp++) {
                const int dd0 = tx + jp * 16;          // < 32
                const float inv = exp2f(-(float)dd0 * L2T);
                const float ang = pos * inv;
                const float cs = cosf(ang);
                const float sn = sinf(ang);
                const float x0 = acc[i][jp]     + bias[n0 + dd0];
                const float x1 = acc[i][jp + 2] + bias[n0 + dd0 + 32];
                outg[base + dd0]      = x0 * cs - x1 * sn;
                outg[base + dd0 + 32] = x0 * sn + x1 * cs;
            }
        } else {
#pragma unroll
            for (int j = 0; j < 4; j++) {
                const int dd = tx + j * 16;
                outg[base + dd] = acc[i][j] + bias[n0 + dd];
            }
        }
    }
}

// ---------------------------------------------------------------------------
// Kernel 2: flash attention (non-causal, key-side padding mask), fp32.
// One CTA = one (b,h) and a 64-query block. 256 threads as 16x16; thread
// (ty,tx) owns query rows ty*4+i and (score-col / head-dim) tx+16*j.
// Online softmax; P staged through smem for the PV GEMM.
// Smem stride 65 -> conflict-free for the column-strided [c][kk] reads.
// ---------------------------------------------------------------------------
__global__ __launch_bounds__(256) void attn_kernel(
    const int* __restrict__ amask, float* __restrict__ out)
{
    extern __shared__ float sm[];
    float* sQ = sm;                 // 64*65
    float* sK = sQ + 64 * 65;       // 64*65
    float* sV = sK + 64 * 65;       // 64*65
    float* sP = sV + 64 * 65;       // 64*65
    float* sMask = sP + 64 * 65;    // 64

    const int tid = threadIdx.x;
    const int ty  = tid >> 4;
    const int tx  = tid & 15;
    const int bh  = blockIdx.y;     // 0..B*H-1
    const int b   = bh / H_;
    const int m0  = blockIdx.x * 64;

    const float* qptr = g_q + (size_t)bh * M_ * DH_;
    const float* kptr = g_k + (size_t)bh * M_ * DH_;
    const float* vptr = g_v + (size_t)bh * M_ * DH_;

    // Load Q tile, pre-scaled by 1/sqrt(DH)
#pragma unroll
    for (int t = 0; t < 16; t++) {
        int idx = tid + t * 256;
        int r = idx >> 6, c = idx & 63;
        sQ[r * 65 + c] = qptr[(size_t)(m0 + r) * DH_ + c] * 0.125f;
    }

    float O[4][4];
    float mrun[4], lrun[4];
#pragma unroll
    for (int i = 0; i < 4; i++) {
        mrun[i] = -1e30f; lrun[i] = 0.0f;
#pragma unroll
        for (int j = 0; j < 4; j++) O[i][j] = 0.0f;
    }

    for (int n0 = 0; n0 < M_; n0 += 64) {
        __syncthreads();   // prev-iter reads of sK/sV/sP complete
#pragma unroll
        for (int t = 0; t < 16; t++) {
            int idx = tid + t * 256;
            int r = idx >> 6, c = idx & 63;
            sK[r * 65 + c] = kptr[(size_t)(n0 + r) * DH_ + c];
            sV[r * 65 + c] = vptr[(size_t)(n0 + r) * DH_ + c];
        }
        if (tid < 64) sMask[tid] = amask[b * M_ + n0 + tid] ? 0.0f : -1e30f;
        __syncthreads();

        // S = Q @ K^T (scaled), 4x4 per thread
        float s[4][4];
#pragma unroll
        for (int i = 0; i < 4; i++)
#pragma unroll
            for (int j = 0; j < 4; j++) s[i][j] = 0.0f;

#pragma unroll 16
        for (int kk = 0; kk < 64; kk++) {
            float a0 = sQ[(ty * 4 + 0) * 65 + kk];
            float a1 = sQ[(ty * 4 + 1) * 65 + kk];
            float a2 = sQ[(ty * 4 + 2) * 65 + kk];
            float a3 = sQ[(ty * 4 + 3) * 65 + kk];
            float b0 = sK[(tx)      * 65 + kk];
            float b1 = sK[(tx + 16) * 65 + kk];
            float b2 = sK[(tx + 32) * 65 + kk];
            float b3 = sK[(tx + 48) * 65 + kk];
            s[0][0] += a0 * b0; s[0][1] += a0 * b1; s[0][2] += a0 * b2; s[0][3] += a0 * b3;
            s[1][0] += a1 * b0; s[1][1] += a1 * b1; s[1][2] += a1 * b2; s[1][3] += a1 * b3;
            s[2][0] += a2 * b0; s[2][1] += a2 * b1; s[2][2] += a2 * b2; s[2][3] += a2 * b3;
            s[3][0] += a3 * b0; s[3][1] += a3 * b1; s[3][2] += a3 * b2; s[3][3] += a3 * b3;
        }

        // key-side mask (additive)
        float madd[4];
#pragma unroll
        for (int j = 0; j < 4; j++) madd[j] = sMask[tx + j * 16];
#pragma unroll
        for (int i = 0; i < 4; i++)
#pragma unroll
            for (int j = 0; j < 4; j++) s[i][j] += madd[j];

        // online softmax update per query row (16 lanes cooperate per row)
#pragma unroll
        for (int i = 0; i < 4; i++) {
            float mx = fmaxf(fmaxf(s[i][0], s[i][1]), fmaxf(s[i][2], s[i][3]));
#pragma unroll
            for (int off = 8; off >= 1; off >>= 1)
                mx = fmaxf(mx, __shfl_xor_sync(0xffffffffu, mx, off));
            const float mnew = fmaxf(mrun[i], mx);
            const float corr = __expf(mrun[i] - mnew);
            float rs = 0.0f;
#pragma unroll
            for (int j = 0; j < 4; j++) {
                float p = __expf(s[i][j] - mnew);
                s[i][j] = p;
                rs += p;
            }
#pragma unroll
            for (int off = 8; off >= 1; off >>= 1)
                rs += __shfl_xor_sync(0xffffffffu, rs, off);
            lrun[i] = lrun[i] * corr + rs;
            mrun[i] = mnew;
#pragma unroll
            for (int j = 0; j < 4; j++) O[i][j] *= corr;
        }

        // stage P, then O += P @ V
#pragma unroll
        for (int i = 0; i < 4; i++)
#pragma unroll
            for (int j = 0; j < 4; j++)
                sP[(ty * 4 + i) * 65 + tx + j * 16] = s[i][j];
        __syncthreads();

#pragma unroll 16
        for (int c = 0; c < 64; c++) {
            float p0 = sP[(ty * 4 + 0) * 65 + c];
            float p1 = sP[(ty * 4 + 1) * 65 + c];
            float p2 = sP[(ty * 4 + 2) * 65 + c];
            float p3 = sP[(ty * 4 + 3) * 65 + c];
            float v0 = sV[c * 65 + tx];
            float v1 = sV[c * 65 + tx + 16];
            float v2 = sV[c * 65 + tx + 32];
            float v3 = sV[c * 65 + tx + 48];
            O[0][0] += p0 * v0; O[0][1] += p0 * v1; O[0][2] += p0 * v2; O[0][3] += p0 * v3;
            O[1][0] += p1 * v0; O[1][1] += p1 * v1; O[1][2] += p1 * v2; O[1][3] += p1 * v3;
            O[2][0] += p2 * v0; O[2][1] += p2 * v1; O[2][2] += p2 * v2; O[2][3] += p2 * v3;
            O[3][0] += p3 * v0; O[3][1] += p3 * v1; O[3][2] += p3 * v2; O[3][3] += p3 * v3;
        }
    }

    // epilogue: normalize and write (b,h,m,dd)
#pragma unroll
    for (int i = 0; i < 4; i++) {
        const float invl = 1.0f / lrun[i];
        const int m = m0 + ty * 4 + i;
        const size_t base = ((size_t)bh * M_ + m) * DH_;
#pragma unroll
        for (int j = 0; j < 4; j++)
            out[base + tx + j * 16] = O[i][j] * invl;
    }
}

// ---------------------------------------------------------------------------
extern "C" void kernel_launch(void* const* d_in, const int* in_sizes, int n_in,
                              void* d_out, int out_size) {
    const float* Pq = (const float*)d_in[0];
    const float* Pk = (const float*)d_in[1];
    const float* Pv = (const float*)d_in[2];
    const float* Vq = (const float*)d_in[3];
    const float* Vk = (const float*)d_in[4];
    const float* Vv = (const float*)d_in[5];
    const float* bq = (const float*)d_in[6];
    const float* bk = (const float*)d_in[7];
    const float* bv = (const float*)d_in[8];
    const int* amask = (const int*)d_in[9];
    const int* pos   = (const int*)d_in[10];
    float* out = (float*)d_out;

    dim3 g1(D_ / 64, (B_ * M_) / 64, 3);   // (16, 64, 3)
    svd_proj_kernel<<<g1, 256>>>(Pq, Pk, Pv, Vq, Vk, Vv, bq, bk, bv, pos);

    const int attn_smem = (4 * 64 * 65 + 64) * (int)sizeof(float);  // 66,816 B
    cudaFuncSetAttribute(attn_kernel, cudaFuncAttributeMaxDynamicSharedMemorySize, attn_smem);
    dim3 g2(M_ / 64, B_ * H_);             // (16, 64)
    attn_kernel<<<g2, 256, attn_smem>>>(amask, out);
}

// round 4
// speedup vs baseline: 2.1249x; 2.1249x over previous
#include <cuda_runtime.h>
#include <cuda_bf16.h>
#include <math.h>
#include <stdint.h>

#define B_  4
#define M_  1024
#define R_  256
#define H_  16
#define DH_ 64
#define D_  1024   // H_*DH_

// bf16 operand buffers (uint4 so accesses are 16B-aligned).
// q,k: (b,h,m,d) with bias+RoPE (q prescaled by 1/8). v: (b,h,d,m) TRANSPOSED, NO bias.
__device__ uint4 g_qbf4[(size_t)B_ * H_ * M_ * DH_ / 8];
__device__ uint4 g_kbf4[(size_t)B_ * H_ * M_ * DH_ / 8];
__device__ uint4 g_vT4 [(size_t)B_ * H_ * DH_ * M_ / 8];

__device__ __forceinline__ uint32_t smem_u32(const void* p) {
    uint32_t a;
    asm("{ .reg .u64 t; cvta.to.shared.u64 t, %1; cvt.u32.u64 %0, t; }" : "=r"(a) : "l"(p));
    return a;
}
#define SWZ(x) ((x) ^ (((x) >> 3) & 0x70))

#define LDMATRIX_X4(r0, r1, r2, r3, addr) \
    asm volatile("ldmatrix.sync.aligned.m8n8.x4.shared.b16 {%0,%1,%2,%3}, [%4];" \
                 : "=r"(r0), "=r"(r1), "=r"(r2), "=r"(r3) : "r"(addr))

#define MMA_16816(d, a, b0, b1) \
    asm volatile("mma.sync.aligned.m16n8k16.row.col.f32.bf16.bf16.f32 " \
                 "{%0,%1,%2,%3}, {%4,%5,%6,%7}, {%8,%9}, {%0,%1,%2,%3};" \
                 : "+f"((d)[0]), "+f"((d)[1]), "+f"((d)[2]), "+f"((d)[3]) \
                 : "r"((a)[0]), "r"((a)[1]), "r"((a)[2]), "r"((a)[3]), "r"(b0), "r"(b1))

__device__ __forceinline__ uint32_t pack_bf16(float lo, float hi) {
    uint32_t r;
    asm("cvt.rn.bf16x2.f32 %0, %1, %2;" : "=r"(r) : "f"(hi), "f"(lo));
    return r;
}

// ---------------------------------------------------------------------------
// Kernel 1: fp32 SVD projection + bias + RoPE -> bf16 operand buffers.
// ---------------------------------------------------------------------------
__global__ __launch_bounds__(256) void svd_proj_kernel(
    const float* __restrict__ Pq, const float* __restrict__ Pk, const float* __restrict__ Pv,
    const float* __restrict__ Vq, const float* __restrict__ Vk, const float* __restrict__ Vv,
    const float* __restrict__ bq, const float* __restrict__ bk,
    const int* __restrict__ pos_ids)
{
    const int sel = blockIdx.z;
    const float* A    = (sel == 0) ? Pq : (sel == 1) ? Pk : Pv;
    const float* Bm   = (sel == 0) ? Vq : (sel == 1) ? Vk : Vv;
    const float* bias = (sel == 0) ? bq : bk;   // v-path: bias added in attention epilogue

    __shared__ float sA[64 * 32];
    __shared__ float sB[32 * 64];
    __shared__ float sT[64 * 65];   // transpose staging for v

    const int tid = threadIdx.x;
    const int ty  = tid >> 4;
    const int tx  = tid & 15;
    const int h   = blockIdx.x;
    const int n0  = h * 64;
    const int bm0 = blockIdx.y * 64;
    const int b   = bm0 / M_;
    const int mbase = bm0 % M_;

    float acc[4][4];
#pragma unroll
    for (int i = 0; i < 4; i++)
#pragma unroll
        for (int j = 0; j < 4; j++) acc[i][j] = 0.0f;

    for (int k0 = 0; k0 < R_; k0 += 32) {
#pragma unroll
        for (int t = 0; t < 8; t++) {
            int idx = tid + t * 256;
            sA[idx] = A[(size_t)(bm0 + (idx >> 5)) * R_ + k0 + (idx & 31)];
        }
#pragma unroll
        for (int t = 0; t < 8; t++) {
            int idx = tid + t * 256;
            sB[idx] = Bm[(size_t)(k0 + (idx >> 6)) * D_ + n0 + (idx & 63)];
        }
        __syncthreads();
#pragma unroll
        for (int kk = 0; kk < 32; kk++) {
            float a0 = sA[(ty * 4 + 0) * 32 + kk];
            float a1 = sA[(ty * 4 + 1) * 32 + kk];
            float a2 = sA[(ty * 4 + 2) * 32 + kk];
            float a3 = sA[(ty * 4 + 3) * 32 + kk];
            float b0 = sB[kk * 64 + tx];
            float b1 = sB[kk * 64 + tx + 16];
            float b2 = sB[kk * 64 + tx + 32];
            float b3 = sB[kk * 64 + tx + 48];
            acc[0][0] += a0 * b0; acc[0][1] += a0 * b1; acc[0][2] += a0 * b2; acc[0][3] += a0 * b3;
            acc[1][0] += a1 * b0; acc[1][1] += a1 * b1; acc[1][2] += a1 * b2; acc[1][3] += a1 * b3;
            acc[2][0] += a2 * b0; acc[2][1] += a2 * b1; acc[2][2] += a2 * b2; acc[2][3] += a2 * b3;
            acc[3][0] += a3 * b0; acc[3][1] += a3 * b1; acc[3][2] += a3 * b2; acc[3][3] += a3 * b3;
        }
        __syncthreads();
    }

    if (sel < 2) {
        // bias + RoPE, bf16, (b,h,m,d). Fold score scale 1/8 into q (exact, power of 2).
        __nv_bfloat16* outb = (__nv_bfloat16*)(sel == 0 ? g_qbf4 : g_kbf4);
        const float qscale = (sel == 0) ? 0.125f : 1.0f;
        const float L2T = 13.287712379549449f / 32.0f;
#pragma unroll
        for (int i = 0; i < 4; i++) {
            const int m = mbase + ty * 4 + i;
            const size_t base = ((size_t)(b * H_ + h) * M_ + m) * DH_;
            const float pos = (float)pos_ids[b * M_ + m];
#pragma unroll
            for (int jp = 0; jp < 2; jp++) {
                const int dd0 = tx + jp * 16;          // < 32
                const float inv = exp2f(-(float)dd0 * L2T);
                const float ang = pos * inv;
                const float cs = cosf(ang);
                const float sn = sinf(ang);
                const float x0 = acc[i][jp]     + bias[n0 + dd0];
                const float x1 = acc[i][jp + 2] + bias[n0 + dd0 + 32];
                outb[base + dd0]      = __float2bfloat16((x0 * cs - x1 * sn) * qscale);
                outb[base + dd0 + 32] = __float2bfloat16((x0 * sn + x1 * cs) * qscale);
            }
        }
    } else {
        // v: NO bias; transpose in smem then write bf16 (b,h,d,m) coalesced.
#pragma unroll
        for (int i = 0; i < 4; i++)
#pragma unroll
            for (int j = 0; j < 4; j++)
                sT[(tx + j * 16) * 65 + ty * 4 + i] = acc[i][j];
        __syncthreads();
#pragma unroll
        for (int t = 0; t < 2; t++) {
            int idx = tid + t * 256;         // 512 uint4 total
            int row = idx >> 3;              // dd 0..63
            int ch  = idx & 7;               // 8 bf16 chunk
            uint32_t u[4];
#pragma unroll
            for (int e = 0; e < 4; e++)
                u[e] = pack_bf16(sT[row * 65 + ch * 8 + 2 * e], sT[row * 65 + ch * 8 + 2 * e + 1]);
            uint4 w; w.x = u[0]; w.y = u[1]; w.z = u[2]; w.w = u[3];
            g_vT4[((size_t)(b * H_ + h) * DH_ + row) * (M_ / 8) + (mbase >> 3) + ch] = w;
        }
    }
}

// ---------------------------------------------------------------------------
// Kernel 2: HMMA (mma.sync m16n8k16 bf16) flash attention.
// CTA = 256 threads (8 warps) = 128 queries of one (b,h). Warp w owns rows
// [16w, 16w+16). KV tile = 64 keys. P stays in registers (D-frag == A-frag).
// ---------------------------------------------------------------------------
#define SQ_OFF    0        // 128 x 128B (bf16 Q, SW128)
#define SK_OFF    16384    //  64 x 128B
#define SV_OFF    24576    //  64 x 128B (V^T: [d][key])
#define SMASK_OFF 32768    //  64 floats
#define SBIAS_OFF 33024    //  64 floats
#define ATTN_SMEM 33280

__global__ __launch_bounds__(256) void attn_mma_kernel(
    const int* __restrict__ amask, const float* __restrict__ bv, float* __restrict__ out)
{
    __shared__ __align__(1024) unsigned char smem[ATTN_SMEM];
    const uint32_t sbase = smem_u32(smem);
    const int tid  = threadIdx.x;
    const int lane = tid & 31;
    const int w    = tid >> 5;
    const int bh   = blockIdx.y;
    const int b    = bh >> 4;
    const int h    = bh & 15;
    const int m0   = blockIdx.x * 128;
    const int lrow = lane & 15;
    const int lcol = lane >> 4;
    const int q2   = (lane & 3) * 2;

    // stage Q (128 rows x 128B, SW128)
    {
        const uint4* qsrc = g_qbf4 + (size_t)(bh * M_ + m0) * 8;
#pragma unroll
        for (int t = 0; t < 4; t++) {
            int idx = tid + t * 256;
            int rr = idx >> 3, c = idx & 7;
            *(uint4*)(smem + SQ_OFF + SWZ(rr * 128 + c * 16)) = qsrc[idx];
        }
    }
    if (tid < 64) ((float*)(smem + SBIAS_OFF))[tid] = bv[h * 64 + tid];
    __syncthreads();

    // Q fragments: [kstep][4 regs], resident for whole CTA lifetime
    uint32_t qf[4][4];
#pragma unroll
    for (int s = 0; s < 4; s++) {
        uint32_t a = sbase + SQ_OFF + SWZ((16 * w + lrow) * 128 + s * 32 + lcol * 16);
        LDMATRIX_X4(qf[s][0], qf[s][1], qf[s][2], qf[s][3], a);
    }

    float O[8][4];
#pragma unroll
    for (int j = 0; j < 8; j++)
#pragma unroll
        for (int e = 0; e < 4; e++) O[j][e] = 0.0f;
    float m0r = -1e30f, m1r = -1e30f, l0 = 0.0f, l1 = 0.0f;

    for (int n0 = 0; n0 < M_; n0 += 64) {
        __syncthreads();   // previous tile fully consumed
        {
            const uint4* ksrc = g_kbf4 + (size_t)(bh * M_ + n0) * 8;
            const uint4* vsrc = g_vT4 + (size_t)bh * (DH_ * M_ / 8) + (n0 >> 3);
#pragma unroll
            for (int t = 0; t < 2; t++) {
                int idx = tid + t * 256;
                int rr = idx >> 3, c = idx & 7;
                *(uint4*)(smem + SK_OFF + SWZ(rr * 128 + c * 16)) = ksrc[idx];
                *(uint4*)(smem + SV_OFF + SWZ(rr * 128 + c * 16)) = vsrc[(size_t)rr * (M_ / 8) + c];
            }
        }
        if (tid < 64)
            ((float*)(smem + SMASK_OFF))[tid] = amask[b * M_ + n0 + tid] ? 0.0f : -1e30f;
        __syncthreads();

        // ---- S = Q @ K^T : 8 n-tiles x 4 k-steps of m16n8k16 ----
        float S[8][4];
#pragma unroll
        for (int j = 0; j < 8; j++)
#pragma unroll
            for (int e = 0; e < 4; e++) S[j][e] = 0.0f;

#pragma unroll
        for (int jj = 0; jj < 4; jj++) {
#pragma unroll
            for (int s = 0; s < 4; s++) {
                uint32_t k0, k1, k2, k3;
                uint32_t a = sbase + SK_OFF + SWZ((jj * 16 + lrow) * 128 + s * 32 + lcol * 16);
                LDMATRIX_X4(k0, k1, k2, k3, a);
                MMA_16816(S[2 * jj],     qf[s], k0, k2);
                MMA_16816(S[2 * jj + 1], qf[s], k1, k3);
            }
        }

        // ---- mask ----
        const float* mf = (const float*)(smem + SMASK_OFF);
#pragma unroll
        for (int j = 0; j < 8; j++) {
            float mv0 = mf[j * 8 + q2], mv1 = mf[j * 8 + q2 + 1];
            S[j][0] += mv0; S[j][1] += mv1; S[j][2] += mv0; S[j][3] += mv1;
        }

        // ---- online softmax (rows t/4 and t/4+8; quad holds a row) ----
        float mx0 = -1e30f, mx1 = -1e30f;
#pragma unroll
        for (int j = 0; j < 8; j++) {
            mx0 = fmaxf(mx0, fmaxf(S[j][0], S[j][1]));
            mx1 = fmaxf(mx1, fmaxf(S[j][2], S[j][3]));
        }
        mx0 = fmaxf(mx0, __shfl_xor_sync(0xffffffffu, mx0, 1));
        mx0 = fmaxf(mx0, __shfl_xor_sync(0xffffffffu, mx0, 2));
        mx1 = fmaxf(mx1, __shfl_xor_sync(0xffffffffu, mx1, 1));
        mx1 = fmaxf(mx1, __shfl_xor_sync(0xffffffffu, mx1, 2));

        const float mn0 = fmaxf(m0r, mx0);
        const float mn1 = fmaxf(m1r, mx1);
        const float c0 = __expf(m0r - mn0);
        const float c1 = __expf(m1r - mn1);
        m0r = mn0; m1r = mn1;

        float rs0 = 0.0f, rs1 = 0.0f;
        uint32_t pa[4][4];   // A-fragments for PV (bf16x2)
#pragma unroll
        for (int s = 0; s < 4; s++) {
#pragma unroll
            for (int half = 0; half < 2; half++) {
                const int j = 2 * s + half;
                float p0 = __expf(S[j][0] - mn0);
                float p1 = __expf(S[j][1] - mn0);
                float p2 = __expf(S[j][2] - mn1);
                float p3 = __expf(S[j][3] - mn1);
                uint32_t u01 = pack_bf16(p0, p1);
                uint32_t u23 = pack_bf16(p2, p3);
                // l from the ROUNDED values (consistency with PV numerator)
                rs0 += __uint_as_float(u01 << 16) + __uint_as_float(u01 & 0xffff0000u);
                rs1 += __uint_as_float(u23 << 16) + __uint_as_float(u23 & 0xffff0000u);
                pa[s][0 + 2 * half] = u01;   // a0 (k-low) / a2 (k-high): row t/4
                pa[s][1 + 2 * half] = u23;   // a1 / a3: row t/4+8
            }
        }
        rs0 += __shfl_xor_sync(0xffffffffu, rs0, 1);
        rs0 += __shfl_xor_sync(0xffffffffu, rs0, 2);
        rs1 += __shfl_xor_sync(0xffffffffu, rs1, 1);
        rs1 += __shfl_xor_sync(0xffffffffu, rs1, 2);
        l0 = l0 * c0 + rs0;
        l1 = l1 * c1 + rs1;

#pragma unroll
        for (int j = 0; j < 8; j++) {
            O[j][0] *= c0; O[j][1] *= c0;
            O[j][2] *= c1; O[j][3] *= c1;
        }

        // ---- O += P @ V^T : 8 d-tiles x 4 k-steps ----
#pragma unroll
        for (int jj = 0; jj < 4; jj++) {
#pragma unroll
            for (int s = 0; s < 4; s++) {
                uint32_t v0, v1, v2, v3;
                uint32_t a = sbase + SV_OFF + SWZ((jj * 16 + lrow) * 128 + s * 32 + lcol * 16);
                LDMATRIX_X4(v0, v1, v2, v3, a);
                MMA_16816(O[2 * jj],     pa[s], v0, v2);
                MMA_16816(O[2 * jj + 1], pa[s], v1, v3);
            }
        }
    }

    // ---- epilogue: out = O/l + bias_v (exact; softmax rows sum to 1) ----
    {
        const float* sb = (const float*)(smem + SBIAS_OFF);
        const float inv0 = 1.0f / l0;
        const float inv1 = 1.0f / l1;
        const int row0 = 16 * w + (lane >> 2);
        const int row1 = row0 + 8;
        float* o0 = out + ((size_t)bh * M_ + m0 + row0) * DH_;
        float* o1 = out + ((size_t)bh * M_ + m0 + row1) * DH_;
#pragma unroll
        for (int j = 0; j < 8; j++) {
            const int col = j * 8 + q2;
            float2 w0, w1;
            w0.x = O[j][0] * inv0 + sb[col];
            w0.y = O[j][1] * inv0 + sb[col + 1];
            w1.x = O[j][2] * inv1 + sb[col];
            w1.y = O[j][3] * inv1 + sb[col + 1];
            *(float2*)(o0 + col) = w0;
            *(float2*)(o1 + col) = w1;
        }
    }
}

// ---------------------------------------------------------------------------
extern "C" void kernel_launch(void* const* d_in, const int* in_sizes, int n_in,
                              void* d_out, int out_size) {
    const float* Pq = (const float*)d_in[0];
    const float* Pk = (const float*)d_in[1];
    const float* Pv = (const float*)d_in[2];
    const float* Vq = (const float*)d_in[3];
    const float* Vk = (const float*)d_in[4];
    const float* Vv = (const float*)d_in[5];
    const float* bq = (const float*)d_in[6];
    const float* bk = (const float*)d_in[7];
    const float* bv = (const float*)d_in[8];
    const int* amask = (const int*)d_in[9];
    const int* pos   = (const int*)d_in[10];
    float* out = (float*)d_out;

    dim3 g1(D_ / 64, (B_ * M_) / 64, 3);   // (16, 64, 3)
    svd_proj_kernel<<<g1, 256>>>(Pq, Pk, Pv, Vq, Vk, Vv, bq, bk, pos);

    dim3 g2(M_ / 128, B_ * H_);            // (8, 64)
    attn_mma_kernel<<<g2, 256>>>(amask, bv, out);
}

// round 5
// speedup vs baseline: 4.6012x; 2.1653x over previous
#include <cuda_runtime.h>
#include <cuda_bf16.h>
#include <math.h>
#include <stdint.h>

#define B_  4
#define M_  1024
#define R_  256
#define H_  16
#define DH_ 64
#define D_  1024   // H_*DH_

// bf16 operand buffers (uint4 so accesses are 16B-aligned).
// q,k: (b,h,m,d) with bias+RoPE (q prescaled by 1/8). v: (b,h,d,m) TRANSPOSED, NO bias.
__device__ uint4 g_qbf4[(size_t)B_ * H_ * M_ * DH_ / 8];
__device__ uint4 g_kbf4[(size_t)B_ * H_ * M_ * DH_ / 8];
__device__ uint4 g_vT4 [(size_t)B_ * H_ * DH_ * M_ / 8];
// prep buffers: P in bf16 (same layout), V transposed to [d][r] bf16 (k-major rows)
__device__ uint4 g_Pbf4[(size_t)3 * B_ * M_ * R_ / 8];
__device__ uint4 g_VT4p[(size_t)3 * D_ * R_ / 8];

__device__ __forceinline__ uint32_t smem_u32(const void* p) {
    uint32_t a;
    asm("{ .reg .u64 t; cvta.to.shared.u64 t, %1; cvt.u32.u64 %0, t; }" : "=r"(a) : "l"(p));
    return a;
}
#define SWZ(x) ((x) ^ (((x) >> 3) & 0x70))

#define LDMATRIX_X4(r0, r1, r2, r3, addr) \
    asm volatile("ldmatrix.sync.aligned.m8n8.x4.shared.b16 {%0,%1,%2,%3}, [%4];" \
                 : "=r"(r0), "=r"(r1), "=r"(r2), "=r"(r3) : "r"(addr))

#define MMA_16816(d, a, b0, b1) \
    asm volatile("mma.sync.aligned.m16n8k16.row.col.f32.bf16.bf16.f32 " \
                 "{%0,%1,%2,%3}, {%4,%5,%6,%7}, {%8,%9}, {%0,%1,%2,%3};" \
                 : "+f"((d)[0]), "+f"((d)[1]), "+f"((d)[2]), "+f"((d)[3]) \
                 : "r"((a)[0]), "r"((a)[1]), "r"((a)[2]), "r"((a)[3]), "r"(b0), "r"(b1))

__device__ __forceinline__ uint32_t pack_bf16(float lo, float hi) {
    uint32_t r;
    asm("cvt.rn.bf16x2.f32 %0, %1, %2;" : "=r"(r) : "f"(hi), "f"(lo));
    return r;
}

// ---------------------------------------------------------------------------
// Prep A: P fp32 -> bf16 (layout unchanged). grid (1024, 3), block 256.
// ---------------------------------------------------------------------------
__global__ __launch_bounds__(256) void convert_P_kernel(
    const float* __restrict__ Pq, const float* __restrict__ Pk, const float* __restrict__ Pv)
{
    const int sel = blockIdx.y;
    const float* src = (sel == 0) ? Pq : (sel == 1) ? Pk : Pv;
    const int idx = blockIdx.x * 256 + threadIdx.x;     // float4 index, 0..262143
    float4 v = ((const float4*)src)[idx];
    uint2 o;
    o.x = pack_bf16(v.x, v.y);
    o.y = pack_bf16(v.z, v.w);
    ((uint2*)g_Pbf4)[(size_t)sel * 262144 + idx] = o;
}

// ---------------------------------------------------------------------------
// Prep B: V (R x D fp32) -> VT (D x R bf16). 32x32 smem tile transpose.
// grid (D/32=32, R/32=8, 3), block (32, 8).
// ---------------------------------------------------------------------------
__global__ __launch_bounds__(256) void transpose_V_kernel(
    const float* __restrict__ Vq, const float* __restrict__ Vk, const float* __restrict__ Vv)
{
    const int sel = blockIdx.z;
    const float* src = (sel == 0) ? Vq : (sel == 1) ? Vk : Vv;
    __nv_bfloat16* dst = (__nv_bfloat16*)g_VT4p + (size_t)sel * D_ * R_;

    __shared__ float t[32][33];
    const int d0 = blockIdx.x * 32;
    const int r0 = blockIdx.y * 32;
    const int tx = threadIdx.x;
    const int ty = threadIdx.y;
#pragma unroll
    for (int i = 0; i < 4; i++) {
        const int row = ty + i * 8;
        t[row][tx] = src[(size_t)(r0 + row) * D_ + d0 + tx];
    }
    __syncthreads();
#pragma unroll
    for (int i = 0; i < 4; i++) {
        const int drow = ty + i * 8;
        dst[(size_t)(d0 + drow) * R_ + r0 + tx] = __float2bfloat16(t[tx][drow]);
    }
}

// ---------------------------------------------------------------------------
// Kernel 1: HMMA projection. CTA = 128 (b,m)-rows x 64 cols (one head), K=256
// in 4 chunks of 64. 8 warps; warp w owns rows [16w,16w+16).
// Epilogue: bias+RoPE -> g_q/g_k (sel<2) or smem transpose -> g_vT4 (sel==2).
// ---------------------------------------------------------------------------
#define PJ_SA    0        // 128 x 128B (P chunk)
#define PJ_SB    16384    //  64 x 128B (VT chunk)
#define PJ_BIAS  24576    //  64 floats
#define PJ_SMEM  33792    // also fits v-transpose staging: 64 x 132 floats

__global__ __launch_bounds__(256) void proj_mma_kernel(
    const float* __restrict__ bq, const float* __restrict__ bk,
    const int* __restrict__ pos_ids)
{
    __shared__ __align__(1024) unsigned char smem[PJ_SMEM];
    const uint32_t sbase = smem_u32(smem);
    const int tid  = threadIdx.x;
    const int lane = tid & 31;
    const int w    = tid >> 5;
    const int lrow = lane & 15;
    const int lcol = lane >> 4;
    const int q2   = (lane & 3) * 2;

    const int bm0 = blockIdx.x * 128;
    const int h   = blockIdx.y;
    const int sel = blockIdx.z;
    const int b   = bm0 >> 10;
    const int mb  = bm0 & (M_ - 1);

    if (sel < 2 && tid < 64) {
        const float* bias = (sel == 0) ? bq : bk;
        ((float*)(smem + PJ_BIAS))[tid] = bias[h * 64 + tid];
    }

    float C[8][4];
#pragma unroll
    for (int j = 0; j < 8; j++)
#pragma unroll
        for (int e = 0; e < 4; e++) C[j][e] = 0.0f;

    const uint4* pbase = g_Pbf4 + (size_t)sel * 131072 + (size_t)bm0 * 32;  // 32 uint4/row
    const uint4* vbase = g_VT4p + (size_t)sel * 32768 + (size_t)(h * 64) * 32;

    for (int k0 = 0; k0 < R_; k0 += 64) {
        __syncthreads();
        const int kc = k0 >> 3;    // uint4 offset within row
        // A: 128 rows x 8 uint4
#pragma unroll
        for (int t = 0; t < 4; t++) {
            int idx = tid + t * 256;
            int rr = idx >> 3, c = idx & 7;
            *(uint4*)(smem + PJ_SA + SWZ(rr * 128 + c * 16)) = pbase[rr * 32 + kc + c];
        }
        // B: 64 rows x 8 uint4
#pragma unroll
        for (int t = 0; t < 2; t++) {
            int idx = tid + t * 256;
            int rr = idx >> 3, c = idx & 7;
            *(uint4*)(smem + PJ_SB + SWZ(rr * 128 + c * 16)) = vbase[rr * 32 + kc + c];
        }
        __syncthreads();

        uint32_t af[4][4];
#pragma unroll
        for (int s = 0; s < 4; s++) {
            uint32_t a = sbase + PJ_SA + SWZ((16 * w + lrow) * 128 + s * 32 + lcol * 16);
            LDMATRIX_X4(af[s][0], af[s][1], af[s][2], af[s][3], a);
        }
#pragma unroll
        for (int jj = 0; jj < 4; jj++) {
#pragma unroll
            for (int s = 0; s < 4; s++) {
                uint32_t b0, b1, b2, b3;
                uint32_t a = sbase + PJ_SB + SWZ((jj * 16 + lrow) * 128 + s * 32 + lcol * 16);
                LDMATRIX_X4(b0, b1, b2, b3, a);
                MMA_16816(C[2 * jj],     af[s], b0, b2);
                MMA_16816(C[2 * jj + 1], af[s], b1, b3);
            }
        }
    }

    const int row0 = 16 * w + (lane >> 2);
    const int row1 = row0 + 8;

    if (sel < 2) {
        // bias + RoPE -> bf16 (b,h,m,d). Fold 1/8 score scale into q.
        const float qscale = (sel == 0) ? 0.125f : 1.0f;
        const float L2T = 13.287712379549449f / 32.0f;
        const float* sb = (const float*)(smem + PJ_BIAS);
        __nv_bfloat16* outb = (__nv_bfloat16*)(sel == 0 ? g_qbf4 : g_kbf4);
        const float pos0 = (float)pos_ids[b * M_ + mb + row0];
        const float pos1 = (float)pos_ids[b * M_ + mb + row1];
        const size_t base0 = ((size_t)(b * H_ + h) * M_ + mb + row0) * DH_;
        const size_t base1 = ((size_t)(b * H_ + h) * M_ + mb + row1) * DH_;
#pragma unroll
        for (int j = 0; j < 4; j++) {
#pragma unroll
            for (int e = 0; e < 2; e++) {
                const int dd0 = j * 8 + q2 + e;     // < 32
                const float inv = exp2f(-(float)dd0 * L2T);
                const float blo = sb[dd0], bhi = sb[dd0 + 32];
                // row0 (acc e), row1 (acc e+2)
                {
                    const float ang = pos0 * inv;
                    const float cs = cosf(ang), sn = sinf(ang);
                    const float x0 = C[j][e] + blo, x1 = C[j + 4][e] + bhi;
                    outb[base0 + dd0]      = __float2bfloat16((x0 * cs - x1 * sn) * qscale);
                    outb[base0 + dd0 + 32] = __float2bfloat16((x0 * sn + x1 * cs) * qscale);
                }
                {
                    const float ang = pos1 * inv;
                    const float cs = cosf(ang), sn = sinf(ang);
                    const float x0 = C[j][e + 2] + blo, x1 = C[j + 4][e + 2] + bhi;
                    outb[base1 + dd0]      = __float2bfloat16((x0 * cs - x1 * sn));
                    outb[base1 + dd0 + 32] = __float2bfloat16((x0 * sn + x1 * cs));
                }
            }
        }
        // note: k-path qscale==1 so the missing *qscale on row1 writes is fine for k;
        // for q (sel==0) we must scale row1 too -> handled below if needed
        if (sel == 0) {
            // row1 writes above missed qscale; rewrite them scaled (cheap, registers intact)
#pragma unroll
            for (int j = 0; j < 4; j++) {
#pragma unroll
                for (int e = 0; e < 2; e++) {
                    const int dd0 = j * 8 + q2 + e;
                    const float inv = exp2f(-(float)dd0 * L2T);
                    const float blo = sb[dd0], bhi = sb[dd0 + 32];
                    const float ang = pos1 * inv;
                    const float cs = cosf(ang), sn = sinf(ang);
                    const float x0 = C[j][e + 2] + blo, x1 = C[j + 4][e + 2] + bhi;
                    outb[base1 + dd0]      = __float2bfloat16((x0 * cs - x1 * sn) * 0.125f);
                    outb[base1 + dd0 + 32] = __float2bfloat16((x0 * sn + x1 * cs) * 0.125f);
                }
            }
        }
    } else {
        // v: stage transpose in smem (64 d x 132 stride floats), write (b,h,d,m) bf16.
        __syncthreads();
        float* sT = (float*)smem;
#pragma unroll
        for (int j = 0; j < 8; j++) {
            const int col = j * 8 + q2;
            sT[col * 132 + row0]       = C[j][0];
            sT[(col + 1) * 132 + row0] = C[j][1];
            sT[col * 132 + row1]       = C[j][2];
            sT[(col + 1) * 132 + row1] = C[j][3];
        }
        __syncthreads();
#pragma unroll
        for (int t = 0; t < 4; t++) {
            int idx = tid + t * 256;      // 1024 uint4: 64 d-rows x 16 chunks
            int dd = idx >> 4, mc = idx & 15;
            const float* s = sT + dd * 132 + mc * 8;
            uint4 wv;
            wv.x = pack_bf16(s[0], s[1]);
            wv.y = pack_bf16(s[2], s[3]);
            wv.z = pack_bf16(s[4], s[5]);
            wv.w = pack_bf16(s[6], s[7]);
            g_vT4[((size_t)(b * H_ + h) * DH_ + dd) * (M_ / 8) + (mb >> 3) + mc] = wv;
        }
    }
}

// ---------------------------------------------------------------------------
// Kernel 2: HMMA flash attention (validated R4 structure).
// __launch_bounds__(256,2): cap regs at 128 -> 2 CTAs/SM.
// ---------------------------------------------------------------------------
#define SQ_OFF    0        // 128 x 128B (bf16 Q, SW128)
#define SK_OFF    16384    //  64 x 128B
#define SV_OFF    24576    //  64 x 128B (V^T: [d][key])
#define SMASK_OFF 32768    //  64 floats
#define SBIAS_OFF 33024    //  64 floats
#define ATTN_SMEM 33280

__global__ __launch_bounds__(256, 2) void attn_mma_kernel(
    const int* __restrict__ amask, const float* __restrict__ bv, float* __restrict__ out)
{
    __shared__ __align__(1024) unsigned char smem[ATTN_SMEM];
    const uint32_t sbase = smem_u32(smem);
    const int tid  = threadIdx.x;
    const int lane = tid & 31;
    const int w    = tid >> 5;
    const int bh   = blockIdx.y;
    const int b    = bh >> 4;
    const int h    = bh & 15;
    const int m0   = blockIdx.x * 128;
    const int lrow = lane & 15;
    const int lcol = lane >> 4;
    const int q2   = (lane & 3) * 2;

    {
        const uint4* qsrc = g_qbf4 + (size_t)(bh * M_ + m0) * 8;
#pragma unroll
        for (int t = 0; t < 4; t++) {
            int idx = tid + t * 256;
            int rr = idx >> 3, c = idx & 7;
            *(uint4*)(smem + SQ_OFF + SWZ(rr * 128 + c * 16)) = qsrc[idx];
        }
    }
    if (tid < 64) ((float*)(smem + SBIAS_OFF))[tid] = bv[h * 64 + tid];
    __syncthreads();

    uint32_t qf[4][4];
#pragma unroll
    for (int s = 0; s < 4; s++) {
        uint32_t a = sbase + SQ_OFF + SWZ((16 * w + lrow) * 128 + s * 32 + lcol * 16);
        LDMATRIX_X4(qf[s][0], qf[s][1], qf[s][2], qf[s][3], a);
    }

    float O[8][4];
#pragma unroll
    for (int j = 0; j < 8; j++)
#pragma unroll
        for (int e = 0; e < 4; e++) O[j][e] = 0.0f;
    float m0r = -1e30f, m1r = -1e30f, l0 = 0.0f, l1 = 0.0f;

    for (int n0 = 0; n0 < M_; n0 += 64) {
        __syncthreads();
        {
            const uint4* ksrc = g_kbf4 + (size_t)(bh * M_ + n0) * 8;
            const uint4* vsrc = g_vT4 + (size_t)bh * (DH_ * M_ / 8) + (n0 >> 3);
#pragma unroll
            for (int t = 0; t < 2; t++) {
                int idx = tid + t * 256;
                int rr = idx >> 3, c = idx & 7;
                *(uint4*)(smem + SK_OFF + SWZ(rr * 128 + c * 16)) = ksrc[idx];
                *(uint4*)(smem + SV_OFF + SWZ(rr * 128 + c * 16)) = vsrc[(size_t)rr * (M_ / 8) + c];
            }
        }
        if (tid < 64)
            ((float*)(smem + SMASK_OFF))[tid] = amask[b * M_ + n0 + tid] ? 0.0f : -1e30f;
        __syncthreads();

        float S[8][4];
#pragma unroll
        for (int j = 0; j < 8; j++)
#pragma unroll
            for (int e = 0; e < 4; e++) S[j][e] = 0.0f;

#pragma unroll
        for (int jj = 0; jj < 4; jj++) {
#pragma unroll
            for (int s = 0; s < 4; s++) {
                uint32_t k0, k1, k2, k3;
                uint32_t a = sbase + SK_OFF + SWZ((jj * 16 + lrow) * 128 + s * 32 + lcol * 16);
                LDMATRIX_X4(k0, k1, k2, k3, a);
                MMA_16816(S[2 * jj],     qf[s], k0, k2);
                MMA_16816(S[2 * jj + 1], qf[s], k1, k3);
            }
        }

        const float* mf = (const float*)(smem + SMASK_OFF);
#pragma unroll
        for (int j = 0; j < 8; j++) {
            float mv0 = mf[j * 8 + q2], mv1 = mf[j * 8 + q2 + 1];
            S[j][0] += mv0; S[j][1] += mv1; S[j][2] += mv0; S[j][3] += mv1;
        }

        float mx0 = -1e30f, mx1 = -1e30f;
#pragma unroll
        for (int j = 0; j < 8; j++) {
            mx0 = fmaxf(mx0, fmaxf(S[j][0], S[j][1]));
            mx1 = fmaxf(mx1, fmaxf(S[j][2], S[j][3]));
        }
        mx0 = fmaxf(mx0, __shfl_xor_sync(0xffffffffu, mx0, 1));
        mx0 = fmaxf(mx0, __shfl_xor_sync(0xffffffffu, mx0, 2));
        mx1 = fmaxf(mx1, __shfl_xor_sync(0xffffffffu, mx1, 1));
        mx1 = fmaxf(mx1, __shfl_xor_sync(0xffffffffu, mx1, 2));

        const float mn0 = fmaxf(m0r, mx0);
        const float mn1 = fmaxf(m1r, mx1);
        const float c0 = __expf(m0r - mn0);
        const float c1 = __expf(m1r - mn1);
        m0r = mn0; m1r = mn1;

        float rs0 = 0.0f, rs1 = 0.0f;
        uint32_t pa[4][4];
#pragma unroll
        for (int s = 0; s < 4; s++) {
#pragma unroll
            for (int half = 0; half < 2; half++) {
                const int j = 2 * s + half;
                float p0 = __expf(S[j][0] - mn0);
                float p1 = __expf(S[j][1] - mn0);
                float p2 = __expf(S[j][2] - mn1);
                float p3 = __expf(S[j][3] - mn1);
                uint32_t u01 = pack_bf16(p0, p1);
                uint32_t u23 = pack_bf16(p2, p3);
                rs0 += __uint_as_float(u01 << 16) + __uint_as_float(u01 & 0xffff0000u);
                rs1 += __uint_as_float(u23 << 16) + __uint_as_float(u23 & 0xffff0000u);
                pa[s][0 + 2 * half] = u01;
                pa[s][1 + 2 * half] = u23;
            }
        }
        rs0 += __shfl_xor_sync(0xffffffffu, rs0, 1);
        rs0 += __shfl_xor_sync(0xffffffffu, rs0, 2);
        rs1 += __shfl_xor_sync(0xffffffffu, rs1, 1);
        rs1 += __shfl_xor_sync(0xffffffffu, rs1, 2);
        l0 = l0 * c0 + rs0;
        l1 = l1 * c1 + rs1;

#pragma unroll
        for (int j = 0; j < 8; j++) {
            O[j][0] *= c0; O[j][1] *= c0;
            O[j][2] *= c1; O[j][3] *= c1;
        }

#pragma unroll
        for (int jj = 0; jj < 4; jj++) {
#pragma unroll
            for (int s = 0; s < 4; s++) {
                uint32_t v0, v1, v2, v3;
                uint32_t a = sbase + SV_OFF + SWZ((jj * 16 + lrow) * 128 + s * 32 + lcol * 16);
                LDMATRIX_X4(v0, v1, v2, v3, a);
                MMA_16816(O[2 * jj],     pa[s], v0, v2);
                MMA_16816(O[2 * jj + 1], pa[s], v1, v3);
            }
        }
    }

    {
        const float* sb = (const float*)(smem + SBIAS_OFF);
        const float inv0 = 1.0f / l0;
        const float inv1 = 1.0f / l1;
        const int row0 = 16 * w + (lane >> 2);
        const int row1 = row0 + 8;
        float* o0 = out + ((size_t)bh * M_ + m0 + row0) * DH_;
        float* o1 = out + ((size_t)bh * M_ + m0 + row1) * DH_;
#pragma unroll
        for (int j = 0; j < 8; j++) {
            const int col = j * 8 + q2;
            float2 w0, w1;
            w0.x = O[j][0] * inv0 + sb[col];
            w0.y = O[j][1] * inv0 + sb[col + 1];
            w1.x = O[j][2] * inv1 + sb[col];
            w1.y = O[j][3] * inv1 + sb[col + 1];
            *(float2*)(o0 + col) = w0;
            *(float2*)(o1 + col) = w1;
        }
    }
}

// ---------------------------------------------------------------------------
extern "C" void kernel_launch(void* const* d_in, const int* in_sizes, int n_in,
                              void* d_out, int out_size) {
    const float* Pq = (const float*)d_in[0];
    const float* Pk = (const float*)d_in[1];
    const float* Pv = (const float*)d_in[2];
    const float* Vq = (const float*)d_in[3];
    const float* Vk = (const float*)d_in[4];
    const float* Vv = (const float*)d_in[5];
    const float* bq = (const float*)d_in[6];
    const float* bk = (const float*)d_in[7];
    const float* bv = (const float*)d_in[8];
    const int* amask = (const int*)d_in[9];
    const int* pos   = (const int*)d_in[10];
    float* out = (float*)d_out;

    convert_P_kernel<<<dim3(1024, 3), 256>>>(Pq, Pk, Pv);
    transpose_V_kernel<<<dim3(32, 8, 3), dim3(32, 8)>>>(Vq, Vk, Vv);

    dim3 g1((B_ * M_) / 128, H_, 3);       // (32, 16, 3)
    proj_mma_kernel<<<g1, 256>>>(bq, bk, pos);

    dim3 g2(M_ / 128, B_ * H_);            // (8, 64)
    attn_mma_kernel<<<g2, 256>>>(amask, bv, out);
}

// round 6
// speedup vs baseline: 5.0756x; 1.1031x over previous
#include <cuda_runtime.h>
#include <cuda_bf16.h>
#include <math.h>
#include <stdint.h>

#define B_  4
#define M_  1024
#define R_  256
#define H_  16
#define DH_ 64
#define D_  1024   // H_*DH_

// q scale folds 1/sqrt(DH) AND log2(e) (softmax computed in exp2 domain)
#define QSCALE 0.18033688011112042f   // 0.125 * log2(e)

// bf16 operand buffers (uint4 so accesses are 16B-aligned).
// q,k: (b,h,m,d) with bias+RoPE (q prescaled by QSCALE). v: (b,h,d,m) TRANSPOSED, NO bias.
__device__ uint4 g_qbf4[(size_t)B_ * H_ * M_ * DH_ / 8];
__device__ uint4 g_kbf4[(size_t)B_ * H_ * M_ * DH_ / 8];
__device__ uint4 g_vT4 [(size_t)B_ * H_ * DH_ * M_ / 8];
// prep buffers: P in bf16 (same layout), V transposed to [d][r] bf16 (k-major rows)
__device__ uint4 g_Pbf4[(size_t)3 * B_ * M_ * R_ / 8];
__device__ uint4 g_VT4p[(size_t)3 * D_ * R_ / 8];

__device__ __forceinline__ uint32_t smem_u32(const void* p) {
    uint32_t a;
    asm("{ .reg .u64 t; cvta.to.shared.u64 t, %1; cvt.u32.u64 %0, t; }" : "=r"(a) : "l"(p));
    return a;
}
#define SWZ(x) ((x) ^ (((x) >> 3) & 0x70))

#define LDMATRIX_X4(r0, r1, r2, r3, addr) \
    asm volatile("ldmatrix.sync.aligned.m8n8.x4.shared.b16 {%0,%1,%2,%3}, [%4];" \
                 : "=r"(r0), "=r"(r1), "=r"(r2), "=r"(r3) : "r"(addr))

#define MMA_16816(d, a, b0, b1) \
    asm volatile("mma.sync.aligned.m16n8k16.row.col.f32.bf16.bf16.f32 " \
                 "{%0,%1,%2,%3}, {%4,%5,%6,%7}, {%8,%9}, {%0,%1,%2,%3};" \
                 : "+f"((d)[0]), "+f"((d)[1]), "+f"((d)[2]), "+f"((d)[3]) \
                 : "r"((a)[0]), "r"((a)[1]), "r"((a)[2]), "r"((a)[3]), "r"(b0), "r"(b1))

#define CP_ASYNC16(dst, src) \
    asm volatile("cp.async.cg.shared.global [%0], [%1], 16;" :: "r"(dst), "l"(src))
#define CP_COMMIT()  asm volatile("cp.async.commit_group;" ::: "memory")
#define CP_WAIT(n)   asm volatile("cp.async.wait_group %0;" :: "n"(n) : "memory")

__device__ __forceinline__ uint32_t pack_bf16(float lo, float hi) {
    uint32_t r;
    asm("cvt.rn.bf16x2.f32 %0, %1, %2;" : "=r"(r) : "f"(hi), "f"(lo));
    return r;
}

// ---------------------------------------------------------------------------
// Prep A: P fp32 -> bf16 (layout unchanged). grid (1024, 3), block 256.
// ---------------------------------------------------------------------------
__global__ __launch_bounds__(256) void convert_P_kernel(
    const float* __restrict__ Pq, const float* __restrict__ Pk, const float* __restrict__ Pv)
{
    const int sel = blockIdx.y;
    const float* src = (sel == 0) ? Pq : (sel == 1) ? Pk : Pv;
    const int idx = blockIdx.x * 256 + threadIdx.x;     // float4 index
    float4 v = ((const float4*)src)[idx];
    uint2 o;
    o.x = pack_bf16(v.x, v.y);
    o.y = pack_bf16(v.z, v.w);
    ((uint2*)g_Pbf4)[(size_t)sel * 262144 + idx] = o;
}

// ---------------------------------------------------------------------------
// Prep B: V (R x D fp32) -> VT (D x R bf16). 32x32 smem tile transpose.
// grid (D/32=32, R/32=8, 3), block (32, 8).
// ---------------------------------------------------------------------------
__global__ __launch_bounds__(256) void transpose_V_kernel(
    const float* __restrict__ Vq, const float* __restrict__ Vk, const float* __restrict__ Vv)
{
    const int sel = blockIdx.z;
    const float* src = (sel == 0) ? Vq : (sel == 1) ? Vk : Vv;
    __nv_bfloat16* dst = (__nv_bfloat16*)g_VT4p + (size_t)sel * D_ * R_;

    __shared__ float t[32][33];
    const int d0 = blockIdx.x * 32;
    const int r0 = blockIdx.y * 32;
    const int tx = threadIdx.x;
    const int ty = threadIdx.y;
#pragma unroll
    for (int i = 0; i < 4; i++) {
        const int row = ty + i * 8;
        t[row][tx] = src[(size_t)(r0 + row) * D_ + d0 + tx];
    }
    __syncthreads();
#pragma unroll
    for (int i = 0; i < 4; i++) {
        const int drow = ty + i * 8;
        dst[(size_t)(d0 + drow) * R_ + r0 + tx] = __float2bfloat16(t[tx][drow]);
    }
}

// ---------------------------------------------------------------------------
// Kernel 1: HMMA projection (validated R5 structure; qscale -> QSCALE).
// ---------------------------------------------------------------------------
#define PJ_SA    0        // 128 x 128B (P chunk)
#define PJ_SB    16384    //  64 x 128B (VT chunk)
#define PJ_BIAS  24576    //  64 floats
#define PJ_SMEM  33792    // also fits v-transpose staging: 64 x 132 floats

__global__ __launch_bounds__(256) void proj_mma_kernel(
    const float* __restrict__ bq, const float* __restrict__ bk,
    const int* __restrict__ pos_ids)
{
    __shared__ __align__(1024) unsigned char smem[PJ_SMEM];
    const uint32_t sbase = smem_u32(smem);
    const int tid  = threadIdx.x;
    const int lane = tid & 31;
    const int w    = tid >> 5;
    const int lrow = lane & 15;
    const int lcol = lane >> 4;
    const int q2   = (lane & 3) * 2;

    const int bm0 = blockIdx.x * 128;
    const int h   = blockIdx.y;
    const int sel = blockIdx.z;
    const int b   = bm0 >> 10;
    const int mb  = bm0 & (M_ - 1);

    if (sel < 2 && tid < 64) {
        const float* bias = (sel == 0) ? bq : bk;
        ((float*)(smem + PJ_BIAS))[tid] = bias[h * 64 + tid];
    }

    float C[8][4];
#pragma unroll
    for (int j = 0; j < 8; j++)
#pragma unroll
        for (int e = 0; e < 4; e++) C[j][e] = 0.0f;

    const uint4* pbase = g_Pbf4 + (size_t)sel * 131072 + (size_t)bm0 * 32;  // 32 uint4/row
    const uint4* vbase = g_VT4p + (size_t)sel * 32768 + (size_t)(h * 64) * 32;

    for (int k0 = 0; k0 < R_; k0 += 64) {
        __syncthreads();
        const int kc = k0 >> 3;
#pragma unroll
        for (int t = 0; t < 4; t++) {
            int idx = tid + t * 256;
            int rr = idx >> 3, c = idx & 7;
            *(uint4*)(smem + PJ_SA + SWZ(rr * 128 + c * 16)) = pbase[rr * 32 + kc + c];
        }
#pragma unroll
        for (int t = 0; t < 2; t++) {
            int idx = tid + t * 256;
            int rr = idx >> 3, c = idx & 7;
            *(uint4*)(smem + PJ_SB + SWZ(rr * 128 + c * 16)) = vbase[rr * 32 + kc + c];
        }
        __syncthreads();

        uint32_t af[4][4];
#pragma unroll
        for (int s = 0; s < 4; s++) {
            uint32_t a = sbase + PJ_SA + SWZ((16 * w + lrow) * 128 + s * 32 + lcol * 16);
            LDMATRIX_X4(af[s][0], af[s][1], af[s][2], af[s][3], a);
        }
#pragma unroll
        for (int jj = 0; jj < 4; jj++) {
#pragma unroll
            for (int s = 0; s < 4; s++) {
                uint32_t b0, b1, b2, b3;
                uint32_t a = sbase + PJ_SB + SWZ((jj * 16 + lrow) * 128 + s * 32 + lcol * 16);
                LDMATRIX_X4(b0, b1, b2, b3, a);
                MMA_16816(C[2 * jj],     af[s], b0, b2);
                MMA_16816(C[2 * jj + 1], af[s], b1, b3);
            }
        }
    }

    const int row0 = 16 * w + (lane >> 2);
    const int row1 = row0 + 8;

    if (sel < 2) {
        const float qscale = (sel == 0) ? QSCALE : 1.0f;
        const float L2T = 13.287712379549449f / 32.0f;
        const float* sb = (const float*)(smem + PJ_BIAS);
        __nv_bfloat16* outb = (__nv_bfloat16*)(sel == 0 ? g_qbf4 : g_kbf4);
        const float pos0 = (float)pos_ids[b * M_ + mb + row0];
        const float pos1 = (float)pos_ids[b * M_ + mb + row1];
        const size_t base0 = ((size_t)(b * H_ + h) * M_ + mb + row0) * DH_;
        const size_t base1 = ((size_t)(b * H_ + h) * M_ + mb + row1) * DH_;
#pragma unroll
        for (int j = 0; j < 4; j++) {
#pragma unroll
            for (int e = 0; e < 2; e++) {
                const int dd0 = j * 8 + q2 + e;     // < 32
                const float inv = exp2f(-(float)dd0 * L2T);
                const float blo = sb[dd0], bhi = sb[dd0 + 32];
                {
                    const float ang = pos0 * inv;
                    const float cs = cosf(ang), sn = sinf(ang);
                    const float x0 = C[j][e] + blo, x1 = C[j + 4][e] + bhi;
                    outb[base0 + dd0]      = __float2bfloat16((x0 * cs - x1 * sn) * qscale);
                    outb[base0 + dd0 + 32] = __float2bfloat16((x0 * sn + x1 * cs) * qscale);
                }
                {
                    const float ang = pos1 * inv;
                    const float cs = cosf(ang), sn = sinf(ang);
                    const float x0 = C[j][e + 2] + blo, x1 = C[j + 4][e + 2] + bhi;
                    outb[base1 + dd0]      = __float2bfloat16((x0 * cs - x1 * sn) * qscale);
                    outb[base1 + dd0 + 32] = __float2bfloat16((x0 * sn + x1 * cs) * qscale);
                }
            }
        }
    } else {
        __syncthreads();
        float* sT = (float*)smem;
#pragma unroll
        for (int j = 0; j < 8; j++) {
            const int col = j * 8 + q2;
            sT[col * 132 + row0]       = C[j][0];
            sT[(col + 1) * 132 + row0] = C[j][1];
            sT[col * 132 + row1]       = C[j][2];
            sT[(col + 1) * 132 + row1] = C[j][3];
        }
        __syncthreads();
#pragma unroll
        for (int t = 0; t < 4; t++) {
            int idx = tid + t * 256;
            int dd = idx >> 4, mc = idx & 15;
            const float* s = sT + dd * 132 + mc * 8;
            uint4 wv;
            wv.x = pack_bf16(s[0], s[1]);
            wv.y = pack_bf16(s[2], s[3]);
            wv.z = pack_bf16(s[4], s[5]);
            wv.w = pack_bf16(s[6], s[7]);
            g_vT4[((size_t)(b * H_ + h) * DH_ + dd) * (M_ / 8) + (mb >> 3) + mc] = wv;
        }
    }
}

// ---------------------------------------------------------------------------
// Kernel 2: HMMA flash attention with cp.async double-buffered KV pipeline.
// exp2-domain softmax (log2e folded into q scale). Dynamic smem.
// ---------------------------------------------------------------------------
#define SQ_OFF    0        // 128 x 128B
#define SK_OFF    16384    // 2 x (64 x 128B)
#define SV_OFF    32768    // 2 x (64 x 128B)
#define SMASK_OFF 49152    // 1024 floats: whole batch-row mask
#define SBIAS_OFF 53248    // 64 floats
#define ATTN_SMEM 53504

__global__ __launch_bounds__(256, 2) void attn_mma_kernel(
    const int* __restrict__ amask, const float* __restrict__ bv, float* __restrict__ out)
{
    extern __shared__ __align__(1024) unsigned char smem[];
    const uint32_t sbase = smem_u32(smem);
    const int tid  = threadIdx.x;
    const int lane = tid & 31;
    const int w    = tid >> 5;
    const int bh   = blockIdx.y;
    const int b    = bh >> 4;
    const int h    = bh & 15;
    const int m0   = blockIdx.x * 128;
    const int lrow = lane & 15;
    const int lcol = lane >> 4;
    const int q2   = (lane & 3) * 2;

    const uint4* kall = g_kbf4 + (size_t)bh * M_ * 8;
    const uint4* vall = g_vT4 + (size_t)bh * (DH_ * M_ / 8);

    // Q tile (once)
    {
        const uint4* qsrc = g_qbf4 + (size_t)(bh * M_ + m0) * 8;
#pragma unroll
        for (int t = 0; t < 4; t++) {
            int idx = tid + t * 256;
            int rr = idx >> 3, c = idx & 7;
            *(uint4*)(smem + SQ_OFF + SWZ(rr * 128 + c * 16)) = qsrc[idx];
        }
    }
    // whole-row mask as float (-1e30 / 0), bias
    {
        float* mrow = (float*)(smem + SMASK_OFF);
#pragma unroll
        for (int t = 0; t < 4; t++) {
            int idx = tid + t * 256;
            mrow[idx] = amask[b * M_ + idx] ? 0.0f : -1e30f;
        }
    }
    if (tid < 64) ((float*)(smem + SBIAS_OFF))[tid] = bv[h * 64 + tid];

    // prologue: issue tile 0 into buffer 0
    {
#pragma unroll
        for (int t = 0; t < 2; t++) {
            int idx = tid + t * 256;
            int rr = idx >> 3, c = idx & 7;
            uint32_t doff = SWZ(rr * 128 + c * 16);
            CP_ASYNC16(sbase + SK_OFF + doff, kall + idx);
            CP_ASYNC16(sbase + SV_OFF + doff, vall + (size_t)rr * (M_ / 8) + c);
        }
    }
    CP_COMMIT();
    __syncthreads();

    uint32_t qf[4][4];
#pragma unroll
    for (int s = 0; s < 4; s++) {
        uint32_t a = sbase + SQ_OFF + SWZ((16 * w + lrow) * 128 + s * 32 + lcol * 16);
        LDMATRIX_X4(qf[s][0], qf[s][1], qf[s][2], qf[s][3], a);
    }

    float O[8][4];
#pragma unroll
    for (int j = 0; j < 8; j++)
#pragma unroll
        for (int e = 0; e < 4; e++) O[j][e] = 0.0f;
    float m0r = -1e30f, m1r = -1e30f, l0 = 0.0f, l1 = 0.0f;

#pragma unroll 1
    for (int it = 0; it < 16; it++) {
        const int buf = it & 1;
        const uint32_t skb = sbase + SK_OFF + buf * 8192;
        const uint32_t svb = sbase + SV_OFF + buf * 8192;

        // issue next tile into the other buffer
        if (it < 15) {
            const int n1 = (it + 1) * 64;
            const uint32_t skn = sbase + SK_OFF + (buf ^ 1) * 8192;
            const uint32_t svn = sbase + SV_OFF + (buf ^ 1) * 8192;
            const uint4* ksrc = kall + (size_t)n1 * 8;
            const uint4* vsrc = vall + (n1 >> 3);
#pragma unroll
            for (int t = 0; t < 2; t++) {
                int idx = tid + t * 256;
                int rr = idx >> 3, c = idx & 7;
                uint32_t doff = SWZ(rr * 128 + c * 16);
                CP_ASYNC16(skn + doff, ksrc + idx);
                CP_ASYNC16(svn + doff, vsrc + (size_t)rr * (M_ / 8) + c);
            }
            CP_COMMIT();
            CP_WAIT(1);
        } else {
            CP_WAIT(0);
        }
        __syncthreads();   // current buffer data visible to all threads

        // ---- S = Q @ K^T ----
        float S[8][4];
#pragma unroll
        for (int j = 0; j < 8; j++)
#pragma unroll
            for (int e = 0; e < 4; e++) S[j][e] = 0.0f;

#pragma unroll
        for (int jj = 0; jj < 4; jj++) {
#pragma unroll
            for (int s = 0; s < 4; s++) {
                uint32_t k0, k1, k2, k3;
                uint32_t a = skb + SWZ((jj * 16 + lrow) * 128 + s * 32 + lcol * 16);
                LDMATRIX_X4(k0, k1, k2, k3, a);
                MMA_16816(S[2 * jj],     qf[s], k0, k2);
                MMA_16816(S[2 * jj + 1], qf[s], k1, k3);
            }
        }

        // ---- mask (from resident whole-row buffer) ----
        const float* mf = (const float*)(smem + SMASK_OFF) + it * 64;
#pragma unroll
        for (int j = 0; j < 8; j++) {
            float mv0 = mf[j * 8 + q2], mv1 = mf[j * 8 + q2 + 1];
            S[j][0] += mv0; S[j][1] += mv1; S[j][2] += mv0; S[j][3] += mv1;
        }

        // ---- online softmax in exp2 domain ----
        float mx0 = -1e30f, mx1 = -1e30f;
#pragma unroll
        for (int j = 0; j < 8; j++) {
            mx0 = fmaxf(mx0, fmaxf(S[j][0], S[j][1]));
            mx1 = fmaxf(mx1, fmaxf(S[j][2], S[j][3]));
        }
        mx0 = fmaxf(mx0, __shfl_xor_sync(0xffffffffu, mx0, 1));
        mx0 = fmaxf(mx0, __shfl_xor_sync(0xffffffffu, mx0, 2));
        mx1 = fmaxf(mx1, __shfl_xor_sync(0xffffffffu, mx1, 1));
        mx1 = fmaxf(mx1, __shfl_xor_sync(0xffffffffu, mx1, 2));

        const float mn0 = fmaxf(m0r, mx0);
        const float mn1 = fmaxf(m1r, mx1);
        const float c0 = exp2f(m0r - mn0);
        const float c1 = exp2f(m1r - mn1);
        m0r = mn0; m1r = mn1;

        float rs0 = 0.0f, rs1 = 0.0f;
        uint32_t pa[4][4];
#pragma unroll
        for (int s = 0; s < 4; s++) {
#pragma unroll
            for (int half = 0; half < 2; half++) {
                const int j = 2 * s + half;
                float p0 = exp2f(S[j][0] - mn0);
                float p1 = exp2f(S[j][1] - mn0);
                float p2 = exp2f(S[j][2] - mn1);
                float p3 = exp2f(S[j][3] - mn1);
                uint32_t u01 = pack_bf16(p0, p1);
                uint32_t u23 = pack_bf16(p2, p3);
                rs0 += __uint_as_float(u01 << 16) + __uint_as_float(u01 & 0xffff0000u);
                rs1 += __uint_as_float(u23 << 16) + __uint_as_float(u23 & 0xffff0000u);
                pa[s][0 + 2 * half] = u01;
                pa[s][1 + 2 * half] = u23;
            }
        }
        rs0 += __shfl_xor_sync(0xffffffffu, rs0, 1);
        rs0 += __shfl_xor_sync(0xffffffffu, rs0, 2);
        rs1 += __shfl_xor_sync(0xffffffffu, rs1, 1);
        rs1 += __shfl_xor_sync(0xffffffffu, rs1, 2);
        l0 = l0 * c0 + rs0;
        l1 = l1 * c1 + rs1;

#pragma unroll
        for (int j = 0; j < 8; j++) {
            O[j][0] *= c0; O[j][1] *= c0;
            O[j][2] *= c1; O[j][3] *= c1;
        }

        // ---- O += P @ V^T ----
#pragma unroll
        for (int jj = 0; jj < 4; jj++) {
#pragma unroll
            for (int s = 0; s < 4; s++) {
                uint32_t v0, v1, v2, v3;
                uint32_t a = svb + SWZ((jj * 16 + lrow) * 128 + s * 32 + lcol * 16);
                LDMATRIX_X4(v0, v1, v2, v3, a);
                MMA_16816(O[2 * jj],     pa[s], v0, v2);
                MMA_16816(O[2 * jj + 1], pa[s], v1, v3);
            }
        }
        __syncthreads();   // readers of this buffer done before iter it+1 refills it
    }

    // ---- epilogue: out = O/l + bias_v ----
    {
        const float* sb = (const float*)(smem + SBIAS_OFF);
        const float inv0 = 1.0f / l0;
        const float inv1 = 1.0f / l1;
        const int row0 = 16 * w + (lane >> 2);
        const int row1 = row0 + 8;
        float* o0 = out + ((size_t)bh * M_ + m0 + row0) * DH_;
        float* o1 = out + ((size_t)bh * M_ + m0 + row1) * DH_;
#pragma unroll
        for (int j = 0; j < 8; j++) {
            const int col = j * 8 + q2;
            float2 w0, w1;
            w0.x = O[j][0] * inv0 + sb[col];
            w0.y = O[j][1] * inv0 + sb[col + 1];
            w1.x = O[j][2] * inv1 + sb[col];
            w1.y = O[j][3] * inv1 + sb[col + 1];
            *(float2*)(o0 + col) = w0;
            *(float2*)(o1 + col) = w1;
        }
    }
}

// ---------------------------------------------------------------------------
extern "C" void kernel_launch(void* const* d_in, const int* in_sizes, int n_in,
                              void* d_out, int out_size) {
    const float* Pq = (const float*)d_in[0];
    const float* Pk = (const float*)d_in[1];
    const float* Pv = (const float*)d_in[2];
    const float* Vq = (const float*)d_in[3];
    const float* Vk = (const float*)d_in[4];
    const float* Vv = (const float*)d_in[5];
    const float* bq = (const float*)d_in[6];
    const float* bk = (const float*)d_in[7];
    const float* bv = (const float*)d_in[8];
    const int* amask = (const int*)d_in[9];
    const int* pos   = (const int*)d_in[10];
    float* out = (float*)d_out;

    convert_P_kernel<<<dim3(1024, 3), 256>>>(Pq, Pk, Pv);
    transpose_V_kernel<<<dim3(32, 8, 3), dim3(32, 8)>>>(Vq, Vk, Vv);

    dim3 g1((B_ * M_) / 128, H_, 3);       // (32, 16, 3)
    proj_mma_kernel<<<g1, 256>>>(bq, bk, pos);

    cudaFuncSetAttribute(attn_mma_kernel, cudaFuncAttributeMaxDynamicSharedMemorySize, ATTN_SMEM);
    dim3 g2(M_ / 128, B_ * H_);            // (8, 64)
    attn_mma_kernel<<<g2, 256, ATTN_SMEM>>>(amask, bv, out);
}